// round 1
// baseline (speedup 1.0000x reference)
#include <cuda_runtime.h>
#include <cuda_fp16.h>

// Problem constants
#define B_ROWS 65536
#define D_DIM  512
#define C_DIM  101
#define E_DIM  8
#define H_DIM  256

#define M_TILE 64
#define KC     64        // GEMM1 K-chunk
#define XPITCH 516       // fp32 pitch for x tile (conflict-free: 516%32=4)
#define W1PITCH 72       // fp16 pitch for W1 chunk (n-major, k contig; 72 halves=144B)
#define W2PITCH 264      // fp16 pitch for W2 tile
#define HGPITCH 264      // fp16 pitch for gated-hidden tile
#define C_PAD  104       // padded output cols (13 n8 tiles)

// Shared memory layout (bytes)
#define SM_XS     0        // 64*516*4   = 132096
#define SM_WBUF   132096   // max(256*72, 104*264)*2 = 54912 ; also reused for Wg fp32 (16KB)
#define SM_HG     187008   // 64*264*2   = 33792
#define SM_GATES  220800   // 64*8*4     = 2048
#define SM_LOGITS 222848   // 64*8*4     = 2048
#define SM_B2     224896   // 808*4      = 3232
#define SMEM_TOTAL 228128

// fp16 weight scratch (converted+transposed once per launch; graph-deterministic)
__device__ __align__(16) __half g_W1h[E_DIM * H_DIM * D_DIM];  // [e][h][d]
__device__ __align__(16) __half g_W2h[E_DIM * C_DIM * H_DIM];  // [e][c][h]

__global__ void cvt_w1_kernel(const float* __restrict__ W1) {
    int idx = blockIdx.x * blockDim.x + threadIdx.x;
    if (idx >= E_DIM * H_DIM * D_DIM) return;
    int d = idx & (D_DIM - 1);
    int h = (idx >> 9) & (H_DIM - 1);
    int e = idx >> 17;
    g_W1h[idx] = __float2half_rn(W1[(e * D_DIM + d) * H_DIM + h]);
}

__global__ void cvt_w2_kernel(const float* __restrict__ W2) {
    int idx = blockIdx.x * blockDim.x + threadIdx.x;
    if (idx >= E_DIM * C_DIM * H_DIM) return;
    int h = idx & (H_DIM - 1);
    int t = idx >> 8;
    int c = t % C_DIM;
    int e = t / C_DIM;
    g_W2h[idx] = __float2half_rn(W2[(e * H_DIM + h) * C_DIM + c]);
}

__device__ __forceinline__ void mma16816(float* c,
                                         unsigned a0, unsigned a1, unsigned a2, unsigned a3,
                                         unsigned b0, unsigned b1) {
    asm volatile(
        "mma.sync.aligned.m16n8k16.row.col.f32.f16.f16.f32 "
        "{%0,%1,%2,%3}, {%4,%5,%6,%7}, {%8,%9}, {%0,%1,%2,%3};\n"
        : "+f"(c[0]), "+f"(c[1]), "+f"(c[2]), "+f"(c[3])
        : "r"(a0), "r"(a1), "r"(a2), "r"(a3), "r"(b0), "r"(b1));
}

// split a float2 into hi/lo fp16 pairs (packed b32 regs)
__device__ __forceinline__ void split2(float2 f, unsigned& hi, unsigned& lo) {
    __half hx = __float2half_rn(f.x);
    __half hy = __float2half_rn(f.y);
    __half lx = __float2half_rn(f.x - __half2float(hx));
    __half ly = __float2half_rn(f.y - __half2float(hy));
    hi = ((unsigned)__half_as_ushort(hy) << 16) | (unsigned)__half_as_ushort(hx);
    lo = ((unsigned)__half_as_ushort(ly) << 16) | (unsigned)__half_as_ushort(lx);
}

__global__ void __launch_bounds__(256, 1)
moe_fused_kernel(const float* __restrict__ x,
                 const float* __restrict__ b1,
                 const float* __restrict__ b2,
                 const float* __restrict__ Wg,
                 const float* __restrict__ bg,
                 float* __restrict__ out) {
    extern __shared__ char smem[];
    float*  xs     = (float*)(smem + SM_XS);
    __half* wbuf   = (__half*)(smem + SM_WBUF);
    float*  wgs    = (float*)(smem + SM_WBUF);   // Wg reuses wbuf before the expert loop
    __half* hg     = (__half*)(smem + SM_HG);
    float*  gates  = (float*)(smem + SM_GATES);
    float*  logits = (float*)(smem + SM_LOGITS);
    float*  b2s    = (float*)(smem + SM_B2);

    const int tid    = threadIdx.x;
    const int wid    = tid >> 5;
    const int lane   = tid & 31;
    const int gid    = lane >> 2;   // group-of-4 id (0..7)
    const int tg     = lane & 3;    // thread-in-group (0..3)
    const int warp_m = wid >> 1;    // 0..3
    const int warp_n = wid & 1;     // 0..1
    const int m0     = blockIdx.x * M_TILE;

    // ---- load x tile [64,512] fp32 into padded smem ----
    {
        const float4* xg = (const float4*)(x + (size_t)m0 * D_DIM);
        for (int i = tid; i < M_TILE * (D_DIM / 4); i += 256) {
            int r  = i >> 7;       // 128 float4 per row
            int c4 = i & 127;
            float4 v = xg[r * 128 + c4];
            *(float4*)&xs[r * XPITCH + c4 * 4] = v;
        }
    }
    for (int i = tid; i < E_DIM * C_DIM; i += 256) b2s[i] = b2[i];
    for (int i = tid; i < D_DIM * E_DIM; i += 256) wgs[i] = Wg[i];
    __syncthreads();

    // ---- gate logits in fp32: thread t -> row t>>2, experts (t&3)*2, +1 ----
    {
        int row = tid >> 2;
        int e0  = (tid & 3) * 2;
        float s0 = 0.f, s1 = 0.f;
        for (int d = 0; d < D_DIM; d += 4) {
            float4 xv = *(const float4*)&xs[row * XPITCH + d];
            float2 w0 = *(const float2*)&wgs[(d + 0) * E_DIM + e0];
            float2 w1 = *(const float2*)&wgs[(d + 1) * E_DIM + e0];
            float2 w2 = *(const float2*)&wgs[(d + 2) * E_DIM + e0];
            float2 w3 = *(const float2*)&wgs[(d + 3) * E_DIM + e0];
            s0 += xv.x * w0.x + xv.y * w1.x + xv.z * w2.x + xv.w * w3.x;
            s1 += xv.x * w0.y + xv.y * w1.y + xv.z * w2.y + xv.w * w3.y;
        }
        logits[row * E_DIM + e0]     = s0 + bg[e0];
        logits[row * E_DIM + e0 + 1] = s1 + bg[e0 + 1];
    }
    __syncthreads();
    // softmax over 8 experts, one thread per row
    if (tid < M_TILE) {
        float l[8], m = -1e30f;
        #pragma unroll
        for (int e = 0; e < 8; e++) { l[e] = logits[tid * 8 + e]; m = fmaxf(m, l[e]); }
        float s = 0.f;
        #pragma unroll
        for (int e = 0; e < 8; e++) { l[e] = __expf(l[e] - m); s += l[e]; }
        float inv = 1.f / s;
        #pragma unroll
        for (int e = 0; e < 8; e++) gates[tid * 8 + e] = l[e] * inv;
    }
    __syncthreads();

    // ---- GEMM2 accumulators persist across experts ----
    float acc2[7][4];
    #pragma unroll
    for (int i = 0; i < 7; i++)
        #pragma unroll
        for (int j = 0; j < 4; j++) acc2[i][j] = 0.f;

    const int NT2    = (warp_n == 0) ? 7 : 6;     // 13 n8 tiles split 7/6
    const int n2base = (warp_n == 0) ? 0 : 56;    // col base for this warp

    for (int e = 0; e < E_DIM; e++) {
        // ---- GEMM1: h = x @ W1[e], accum fp32 in regs (hi+lo split A) ----
        float acc1[16][4];
        #pragma unroll
        for (int i = 0; i < 16; i++)
            #pragma unroll
            for (int j = 0; j < 4; j++) acc1[i][j] = 0.f;

        const __half* w1e = g_W1h + (size_t)e * H_DIM * D_DIM;
        for (int kc = 0; kc < D_DIM; kc += KC) {
            // stage W1 chunk: 256 rows(h) x 64(d), k-contiguous, uint2 granular
            for (int i = tid; i < H_DIM * (KC / 4); i += 256) {
                int r = i >> 4;   // 16 uint2 per row
                int c = i & 15;
                uint2 v = *(const uint2*)(w1e + r * D_DIM + kc + c * 4);
                *(uint2*)&wbuf[r * W1PITCH + c * 4] = v;
            }
            __syncthreads();
            #pragma unroll
            for (int ks = 0; ks < KC; ks += 16) {
                const int r0 = warp_m * 16 + gid;
                const int xc = kc + ks + tg * 2;
                float2 f0 = *(const float2*)&xs[r0 * XPITCH + xc];
                float2 f1 = *(const float2*)&xs[(r0 + 8) * XPITCH + xc];
                float2 f2 = *(const float2*)&xs[r0 * XPITCH + xc + 8];
                float2 f3 = *(const float2*)&xs[(r0 + 8) * XPITCH + xc + 8];
                unsigned ah0, al0, ah1, al1, ah2, al2, ah3, al3;
                split2(f0, ah0, al0);
                split2(f1, ah1, al1);
                split2(f2, ah2, al2);
                split2(f3, ah3, al3);
                #pragma unroll
                for (int nt = 0; nt < 16; nt++) {
                    int n = warp_n * 128 + nt * 8 + gid;
                    unsigned b0 = *(const unsigned*)&wbuf[n * W1PITCH + ks + tg * 2];
                    unsigned b1r = *(const unsigned*)&wbuf[n * W1PITCH + ks + 8 + tg * 2];
                    mma16816(acc1[nt], ah0, ah1, ah2, ah3, b0, b1r);
                    mma16816(acc1[nt], al0, al1, al2, al3, b0, b1r);
                }
            }
            __syncthreads();
        }

        // ---- epilogue: +b1, relu, *gate -> hg (fp16) ----
        {
            const int r0  = warp_m * 16 + gid;
            float ge0 = gates[r0 * 8 + e];
            float ge1 = gates[(r0 + 8) * 8 + e];
            #pragma unroll
            for (int nt = 0; nt < 16; nt++) {
                int col = warp_n * 128 + nt * 8 + tg * 2;
                float2 bb = *(const float2*)&b1[e * H_DIM + col];
                float v0 = fmaxf(acc1[nt][0] + bb.x, 0.f) * ge0;
                float v1 = fmaxf(acc1[nt][1] + bb.y, 0.f) * ge0;
                float v2 = fmaxf(acc1[nt][2] + bb.x, 0.f) * ge1;
                float v3 = fmaxf(acc1[nt][3] + bb.y, 0.f) * ge1;
                *(__half2*)&hg[r0 * HGPITCH + col]       = __floats2half2_rn(v0, v1);
                *(__half2*)&hg[(r0 + 8) * HGPITCH + col] = __floats2half2_rn(v2, v3);
            }
        }

        // ---- stage W2[e]: 104(c,padded) x 256(h), uint4 granular ----
        {
            const __half* w2e = g_W2h + (size_t)e * C_DIM * H_DIM;
            for (int i = tid; i < C_PAD * 32; i += 256) {
                int r = i >> 5;   // 32 uint4 per row
                int c = i & 31;
                uint4 v;
                if (r < C_DIM) v = *(const uint4*)(w2e + r * H_DIM + c * 8);
                else           v = make_uint4(0u, 0u, 0u, 0u);
                *(uint4*)&wbuf[r * W2PITCH + c * 8] = v;
            }
        }
        __syncthreads();

        // ---- GEMM2: acc2 += hg @ W2[e]^T-layout ----
        #pragma unroll
        for (int ks = 0; ks < H_DIM; ks += 16) {
            const int r0 = warp_m * 16 + gid;
            unsigned a0 = *(const unsigned*)&hg[r0 * HGPITCH + ks + tg * 2];
            unsigned a1 = *(const unsigned*)&hg[(r0 + 8) * HGPITCH + ks + tg * 2];
            unsigned a2 = *(const unsigned*)&hg[r0 * HGPITCH + ks + 8 + tg * 2];
            unsigned a3 = *(const unsigned*)&hg[(r0 + 8) * HGPITCH + ks + 8 + tg * 2];
            #pragma unroll
            for (int nt = 0; nt < 7; nt++) {
                if (nt < NT2) {
                    int n = n2base + nt * 8 + gid;
                    unsigned b0 = *(const unsigned*)&wbuf[n * W2PITCH + ks + tg * 2];
                    unsigned b1r = *(const unsigned*)&wbuf[n * W2PITCH + ks + 8 + tg * 2];
                    mma16816(acc2[nt], a0, a1, a2, a3, b0, b1r);
                }
            }
        }
        __syncthreads();
    }

    // ---- final store: out = acc2 + sum_e g[e]*b2[e][c] ----
    {
        const int r0 = warp_m * 16 + gid;
        const float* gr0 = &gates[r0 * 8];
        const float* gr1 = &gates[(r0 + 8) * 8];
        #pragma unroll
        for (int nt = 0; nt < 7; nt++) {
            if (nt < NT2) {
                int col = n2base + nt * 8 + tg * 2;
                #pragma unroll
                for (int cc = 0; cc < 2; cc++) {
                    int c = col + cc;
                    if (c < C_DIM) {
                        float bias0 = 0.f, bias1 = 0.f;
                        #pragma unroll
                        for (int ee = 0; ee < 8; ee++) {
                            float bv = b2s[ee * C_DIM + c];
                            bias0 += gr0[ee] * bv;
                            bias1 += gr1[ee] * bv;
                        }
                        out[(size_t)(m0 + r0) * C_DIM + c]     = acc2[nt][cc] + bias0;
                        out[(size_t)(m0 + r0 + 8) * C_DIM + c] = acc2[nt][2 + cc] + bias1;
                    }
                }
            }
        }
    }
}

extern "C" void kernel_launch(void* const* d_in, const int* in_sizes, int n_in,
                              void* d_out, int out_size) {
    (void)in_sizes; (void)n_in; (void)out_size;
    const float* x  = (const float*)d_in[0];
    const float* W1 = (const float*)d_in[1];
    const float* b1 = (const float*)d_in[2];
    const float* W2 = (const float*)d_in[3];
    const float* b2 = (const float*)d_in[4];
    const float* Wg = (const float*)d_in[5];
    const float* bg = (const float*)d_in[6];
    float* out = (float*)d_out;

    cvt_w1_kernel<<<(E_DIM * H_DIM * D_DIM + 255) / 256, 256>>>(W1);
    cvt_w2_kernel<<<(E_DIM * C_DIM * H_DIM + 255) / 256, 256>>>(W2);

    cudaFuncSetAttribute(moe_fused_kernel,
                         cudaFuncAttributeMaxDynamicSharedMemorySize, SMEM_TOTAL);
    moe_fused_kernel<<<B_ROWS / M_TILE, 256, SMEM_TOTAL>>>(x, b1, b2, Wg, bg, out);
}

// round 2
// speedup vs baseline: 1.0005x; 1.0005x over previous
#include <cuda_runtime.h>
#include <cuda_fp16.h>

// Problem constants
#define B_ROWS 65536
#define D_DIM  512
#define C_DIM  101
#define E_DIM  8
#define H_DIM  256

#define M_TILE 64
#define KC     64        // GEMM1 K-chunk
#define XPITCH 516       // fp32 pitch for x tile (conflict-free: 516%32=4)
#define W1PITCH 72       // fp16 pitch for W1 chunk (n-major, k contig; 72 halves=144B)
#define W2PITCH 264      // fp16 pitch for W2 tile
#define HGPITCH 264      // fp16 pitch for gated-hidden tile
#define C_PAD  104       // padded output cols (13 n8 tiles)

// Shared memory layout (bytes)
#define SM_XS     0        // 64*516*4   = 132096
#define SM_WBUF   132096   // max(256*72, 104*264)*2 = 54912 ; also reused for Wg fp32 (16KB)
#define SM_HG     187008   // 64*264*2   = 33792
#define SM_GATES  220800   // 64*8*4     = 2048
#define SM_LOGITS 222848   // 64*8*4     = 2048
#define SM_B2     224896   // 808*4      = 3232
#define SMEM_TOTAL 228128

// fp16 weight scratch (converted+transposed once per launch; graph-deterministic)
__device__ __align__(16) __half g_W1h[E_DIM * H_DIM * D_DIM];  // [e][h][d]
__device__ __align__(16) __half g_W2h[E_DIM * C_DIM * H_DIM];  // [e][c][h]

__global__ void cvt_w1_kernel(const float* __restrict__ W1) {
    int idx = blockIdx.x * blockDim.x + threadIdx.x;
    if (idx >= E_DIM * H_DIM * D_DIM) return;
    int d = idx & (D_DIM - 1);
    int h = (idx >> 9) & (H_DIM - 1);
    int e = idx >> 17;
    g_W1h[idx] = __float2half_rn(W1[(e * D_DIM + d) * H_DIM + h]);
}

__global__ void cvt_w2_kernel(const float* __restrict__ W2) {
    int idx = blockIdx.x * blockDim.x + threadIdx.x;
    if (idx >= E_DIM * C_DIM * H_DIM) return;
    int h = idx & (H_DIM - 1);
    int t = idx >> 8;
    int c = t % C_DIM;
    int e = t / C_DIM;
    g_W2h[idx] = __float2half_rn(W2[(e * H_DIM + h) * C_DIM + c]);
}

__device__ __forceinline__ void mma16816(float* c,
                                         unsigned a0, unsigned a1, unsigned a2, unsigned a3,
                                         unsigned b0, unsigned b1) {
    asm volatile(
        "mma.sync.aligned.m16n8k16.row.col.f32.f16.f16.f32 "
        "{%0,%1,%2,%3}, {%4,%5,%6,%7}, {%8,%9}, {%0,%1,%2,%3};\n"
        : "+f"(c[0]), "+f"(c[1]), "+f"(c[2]), "+f"(c[3])
        : "r"(a0), "r"(a1), "r"(a2), "r"(a3), "r"(b0), "r"(b1));
}

// split a float2 into hi/lo fp16 pairs (packed b32 regs)
__device__ __forceinline__ void split2(float2 f, unsigned& hi, unsigned& lo) {
    __half hx = __float2half_rn(f.x);
    __half hy = __float2half_rn(f.y);
    __half lx = __float2half_rn(f.x - __half2float(hx));
    __half ly = __float2half_rn(f.y - __half2float(hy));
    hi = ((unsigned)__half_as_ushort(hy) << 16) | (unsigned)__half_as_ushort(hx);
    lo = ((unsigned)__half_as_ushort(ly) << 16) | (unsigned)__half_as_ushort(lx);
}

__global__ void __launch_bounds__(256, 1)
moe_fused_kernel(const float* __restrict__ x,
                 const float* __restrict__ b1,
                 const float* __restrict__ b2,
                 const float* __restrict__ Wg,
                 const float* __restrict__ bg,
                 float* __restrict__ out) {
    extern __shared__ char smem[];
    float*  xs     = (float*)(smem + SM_XS);
    __half* wbuf   = (__half*)(smem + SM_WBUF);
    float*  wgs    = (float*)(smem + SM_WBUF);   // Wg reuses wbuf before the expert loop
    __half* hg     = (__half*)(smem + SM_HG);
    float*  gates  = (float*)(smem + SM_GATES);
    float*  logits = (float*)(smem + SM_LOGITS);
    float*  b2s    = (float*)(smem + SM_B2);

    const int tid    = threadIdx.x;
    const int wid    = tid >> 5;
    const int lane   = tid & 31;
    const int gid    = lane >> 2;   // group-of-4 id (0..7)
    const int tg     = lane & 3;    // thread-in-group (0..3)
    const int warp_m = wid >> 1;    // 0..3
    const int warp_n = wid & 1;     // 0..1
    const int m0     = blockIdx.x * M_TILE;

    // ---- load x tile [64,512] fp32 into padded smem ----
    {
        const float4* xg = (const float4*)(x + (size_t)m0 * D_DIM);
        for (int i = tid; i < M_TILE * (D_DIM / 4); i += 256) {
            int r  = i >> 7;       // 128 float4 per row
            int c4 = i & 127;
            float4 v = xg[r * 128 + c4];
            *(float4*)&xs[r * XPITCH + c4 * 4] = v;
        }
    }
    for (int i = tid; i < E_DIM * C_DIM; i += 256) b2s[i] = b2[i];
    for (int i = tid; i < D_DIM * E_DIM; i += 256) wgs[i] = Wg[i];
    __syncthreads();

    // ---- gate logits in fp32: thread t -> row t>>2, experts (t&3)*2, +1 ----
    {
        int row = tid >> 2;
        int e0  = (tid & 3) * 2;
        float s0 = 0.f, s1 = 0.f;
        for (int d = 0; d < D_DIM; d += 4) {
            float4 xv = *(const float4*)&xs[row * XPITCH + d];
            float2 w0 = *(const float2*)&wgs[(d + 0) * E_DIM + e0];
            float2 w1 = *(const float2*)&wgs[(d + 1) * E_DIM + e0];
            float2 w2 = *(const float2*)&wgs[(d + 2) * E_DIM + e0];
            float2 w3 = *(const float2*)&wgs[(d + 3) * E_DIM + e0];
            s0 += xv.x * w0.x + xv.y * w1.x + xv.z * w2.x + xv.w * w3.x;
            s1 += xv.x * w0.y + xv.y * w1.y + xv.z * w2.y + xv.w * w3.y;
        }
        logits[row * E_DIM + e0]     = s0 + bg[e0];
        logits[row * E_DIM + e0 + 1] = s1 + bg[e0 + 1];
    }
    __syncthreads();
    // softmax over 8 experts, one thread per row
    if (tid < M_TILE) {
        float l[8], m = -1e30f;
        #pragma unroll
        for (int e = 0; e < 8; e++) { l[e] = logits[tid * 8 + e]; m = fmaxf(m, l[e]); }
        float s = 0.f;
        #pragma unroll
        for (int e = 0; e < 8; e++) { l[e] = __expf(l[e] - m); s += l[e]; }
        float inv = 1.f / s;
        #pragma unroll
        for (int e = 0; e < 8; e++) gates[tid * 8 + e] = l[e] * inv;
    }
    __syncthreads();

    // ---- GEMM2 accumulators persist across experts ----
    float acc2[7][4];
    #pragma unroll
    for (int i = 0; i < 7; i++)
        #pragma unroll
        for (int j = 0; j < 4; j++) acc2[i][j] = 0.f;

    const int NT2    = (warp_n == 0) ? 7 : 6;     // 13 n8 tiles split 7/6
    const int n2base = (warp_n == 0) ? 0 : 56;    // col base for this warp

    for (int e = 0; e < E_DIM; e++) {
        // ---- GEMM1: h = x @ W1[e], accum fp32 in regs (hi+lo split A) ----
        float acc1[16][4];
        #pragma unroll
        for (int i = 0; i < 16; i++)
            #pragma unroll
            for (int j = 0; j < 4; j++) acc1[i][j] = 0.f;

        const __half* w1e = g_W1h + (size_t)e * H_DIM * D_DIM;
        for (int kc = 0; kc < D_DIM; kc += KC) {
            // stage W1 chunk: 256 rows(h) x 64(d), k-contiguous, uint2 granular
            for (int i = tid; i < H_DIM * (KC / 4); i += 256) {
                int r = i >> 4;   // 16 uint2 per row
                int c = i & 15;
                uint2 v = *(const uint2*)(w1e + r * D_DIM + kc + c * 4);
                *(uint2*)&wbuf[r * W1PITCH + c * 4] = v;
            }
            __syncthreads();
            #pragma unroll
            for (int ks = 0; ks < KC; ks += 16) {
                const int r0 = warp_m * 16 + gid;
                const int xc = kc + ks + tg * 2;
                float2 f0 = *(const float2*)&xs[r0 * XPITCH + xc];
                float2 f1 = *(const float2*)&xs[(r0 + 8) * XPITCH + xc];
                float2 f2 = *(const float2*)&xs[r0 * XPITCH + xc + 8];
                float2 f3 = *(const float2*)&xs[(r0 + 8) * XPITCH + xc + 8];
                unsigned ah0, al0, ah1, al1, ah2, al2, ah3, al3;
                split2(f0, ah0, al0);
                split2(f1, ah1, al1);
                split2(f2, ah2, al2);
                split2(f3, ah3, al3);
                #pragma unroll
                for (int nt = 0; nt < 16; nt++) {
                    int n = warp_n * 128 + nt * 8 + gid;
                    unsigned b0 = *(const unsigned*)&wbuf[n * W1PITCH + ks + tg * 2];
                    unsigned b1r = *(const unsigned*)&wbuf[n * W1PITCH + ks + 8 + tg * 2];
                    mma16816(acc1[nt], ah0, ah1, ah2, ah3, b0, b1r);
                    mma16816(acc1[nt], al0, al1, al2, al3, b0, b1r);
                }
            }
            __syncthreads();
        }

        // ---- epilogue: +b1, relu, *gate -> hg (fp16) ----
        {
            const int r0  = warp_m * 16 + gid;
            float ge0 = gates[r0 * 8 + e];
            float ge1 = gates[(r0 + 8) * 8 + e];
            #pragma unroll
            for (int nt = 0; nt < 16; nt++) {
                int col = warp_n * 128 + nt * 8 + tg * 2;
                float2 bb = *(const float2*)&b1[e * H_DIM + col];
                float v0 = fmaxf(acc1[nt][0] + bb.x, 0.f) * ge0;
                float v1 = fmaxf(acc1[nt][1] + bb.y, 0.f) * ge0;
                float v2 = fmaxf(acc1[nt][2] + bb.x, 0.f) * ge1;
                float v3 = fmaxf(acc1[nt][3] + bb.y, 0.f) * ge1;
                *(__half2*)&hg[r0 * HGPITCH + col]       = __floats2half2_rn(v0, v1);
                *(__half2*)&hg[(r0 + 8) * HGPITCH + col] = __floats2half2_rn(v2, v3);
            }
        }

        // ---- stage W2[e]: 104(c,padded) x 256(h), uint4 granular ----
        {
            const __half* w2e = g_W2h + (size_t)e * C_DIM * H_DIM;
            for (int i = tid; i < C_PAD * 32; i += 256) {
                int r = i >> 5;   // 32 uint4 per row
                int c = i & 31;
                uint4 v;
                if (r < C_DIM) v = *(const uint4*)(w2e + r * H_DIM + c * 8);
                else           v = make_uint4(0u, 0u, 0u, 0u);
                *(uint4*)&wbuf[r * W2PITCH + c * 8] = v;
            }
        }
        __syncthreads();

        // ---- GEMM2: acc2 += hg @ W2[e]^T-layout ----
        #pragma unroll
        for (int ks = 0; ks < H_DIM; ks += 16) {
            const int r0 = warp_m * 16 + gid;
            unsigned a0 = *(const unsigned*)&hg[r0 * HGPITCH + ks + tg * 2];
            unsigned a1 = *(const unsigned*)&hg[(r0 + 8) * HGPITCH + ks + tg * 2];
            unsigned a2 = *(const unsigned*)&hg[r0 * HGPITCH + ks + 8 + tg * 2];
            unsigned a3 = *(const unsigned*)&hg[(r0 + 8) * HGPITCH + ks + 8 + tg * 2];
            #pragma unroll
            for (int nt = 0; nt < 7; nt++) {
                if (nt < NT2) {
                    int n = n2base + nt * 8 + gid;
                    unsigned b0 = *(const unsigned*)&wbuf[n * W2PITCH + ks + tg * 2];
                    unsigned b1r = *(const unsigned*)&wbuf[n * W2PITCH + ks + 8 + tg * 2];
                    mma16816(acc2[nt], a0, a1, a2, a3, b0, b1r);
                }
            }
        }
        __syncthreads();
    }

    // ---- final store: out = acc2 + sum_e g[e]*b2[e][c] ----
    {
        const int r0 = warp_m * 16 + gid;
        const float* gr0 = &gates[r0 * 8];
        const float* gr1 = &gates[(r0 + 8) * 8];
        #pragma unroll
        for (int nt = 0; nt < 7; nt++) {
            if (nt < NT2) {
                int col = n2base + nt * 8 + tg * 2;
                #pragma unroll
                for (int cc = 0; cc < 2; cc++) {
                    int c = col + cc;
                    if (c < C_DIM) {
                        float bias0 = 0.f, bias1 = 0.f;
                        #pragma unroll
                        for (int ee = 0; ee < 8; ee++) {
                            float bv = b2s[ee * C_DIM + c];
                            bias0 += gr0[ee] * bv;
                            bias1 += gr1[ee] * bv;
                        }
                        out[(size_t)(m0 + r0) * C_DIM + c]     = acc2[nt][cc] + bias0;
                        out[(size_t)(m0 + r0 + 8) * C_DIM + c] = acc2[nt][2 + cc] + bias1;
                    }
                }
            }
        }
    }
}

extern "C" void kernel_launch(void* const* d_in, const int* in_sizes, int n_in,
                              void* d_out, int out_size) {
    (void)in_sizes; (void)n_in; (void)out_size;
    const float* x  = (const float*)d_in[0];
    const float* W1 = (const float*)d_in[1];
    const float* b1 = (const float*)d_in[2];
    const float* W2 = (const float*)d_in[3];
    const float* b2 = (const float*)d_in[4];
    const float* Wg = (const float*)d_in[5];
    const float* bg = (const float*)d_in[6];
    float* out = (float*)d_out;

    cvt_w1_kernel<<<(E_DIM * H_DIM * D_DIM + 255) / 256, 256>>>(W1);
    cvt_w2_kernel<<<(E_DIM * C_DIM * H_DIM + 255) / 256, 256>>>(W2);

    cudaFuncSetAttribute(moe_fused_kernel,
                         cudaFuncAttributeMaxDynamicSharedMemorySize, SMEM_TOTAL);
    moe_fused_kernel<<<B_ROWS / M_TILE, 256, SMEM_TOTAL>>>(x, b1, b2, Wg, bg, out);
}

// round 3
// speedup vs baseline: 1.0340x; 1.0334x over previous
#include <cuda_runtime.h>
#include <cuda_fp16.h>

// Problem constants
#define B_ROWS 65536
#define D_DIM  512
#define C_DIM  101
#define E_DIM  8
#define H_DIM  256

#define M_TILE 64
#define KC     64        // GEMM1 K-chunk
#define XP     520       // fp16 pitch for xhi/xlo (1040B; 1040%128=16 -> LDSM conflict-free)
#define W1P    72        // fp16 pitch W1 chunk (144B; %128=16)
#define W2P    264       // fp16 pitch W2 tile (528B; %128=16)
#define HGP    264       // fp16 pitch hidden tile
#define C_PAD  112       // padded output cols (14 n8 tiles, 7 per N-warp)

// Shared memory layout (bytes)
#define SM_XHI   0        // 64*520*2 = 66560
#define SM_XLO   66560    // 66560
#define SM_WBUF  133120   // max(256*72, 112*264)*2 = 59136 ; also Wg fp32 (16KB) pre-loop
#define SM_HG    192256   // 64*264*2 = 33792
#define SM_GL    226048   // 64*8*4 = 2048 (logits, then gates in place)
#define SM_B2    228096   // 808*4  = 3232
#define SMEM_TOTAL 231328

// fp16 weight scratch (converted+transposed once per launch; graph-deterministic)
__device__ __align__(16) __half g_W1h[E_DIM * H_DIM * D_DIM];  // [e][h][d]
__device__ __align__(16) __half g_W2h[E_DIM * C_DIM * H_DIM];  // [e][c][h]

__global__ void cvt_w1_kernel(const float* __restrict__ W1) {
    int idx = blockIdx.x * blockDim.x + threadIdx.x;
    if (idx >= E_DIM * H_DIM * D_DIM) return;
    int d = idx & (D_DIM - 1);
    int h = (idx >> 9) & (H_DIM - 1);
    int e = idx >> 17;
    g_W1h[idx] = __float2half_rn(W1[(e * D_DIM + d) * H_DIM + h]);
}

__global__ void cvt_w2_kernel(const float* __restrict__ W2) {
    int idx = blockIdx.x * blockDim.x + threadIdx.x;
    if (idx >= E_DIM * C_DIM * H_DIM) return;
    int h = idx & (H_DIM - 1);
    int t = idx >> 8;
    int c = t % C_DIM;
    int e = t / C_DIM;
    g_W2h[idx] = __float2half_rn(W2[(e * H_DIM + h) * C_DIM + c]);
}

__device__ __forceinline__ void mma16816(float* c,
                                         unsigned a0, unsigned a1, unsigned a2, unsigned a3,
                                         unsigned b0, unsigned b1) {
    asm volatile(
        "mma.sync.aligned.m16n8k16.row.col.f32.f16.f16.f32 "
        "{%0,%1,%2,%3}, {%4,%5,%6,%7}, {%8,%9}, {%0,%1,%2,%3};\n"
        : "+f"(c[0]), "+f"(c[1]), "+f"(c[2]), "+f"(c[3])
        : "r"(a0), "r"(a1), "r"(a2), "r"(a3), "r"(b0), "r"(b1));
}

__device__ __forceinline__ void ldsm_x4(unsigned& r0, unsigned& r1, unsigned& r2,
                                        unsigned& r3, unsigned addr) {
    asm volatile("ldmatrix.sync.aligned.m8n8.x4.shared.b16 {%0,%1,%2,%3}, [%4];\n"
                 : "=r"(r0), "=r"(r1), "=r"(r2), "=r"(r3) : "r"(addr));
}

__device__ __forceinline__ void ldsm_x2(unsigned& r0, unsigned& r1, unsigned addr) {
    asm volatile("ldmatrix.sync.aligned.m8n8.x2.shared.b16 {%0,%1}, [%2];\n"
                 : "=r"(r0), "=r"(r1) : "r"(addr));
}

__device__ __forceinline__ unsigned su(const void* p) {
    return (unsigned)__cvta_generic_to_shared(p);
}

__global__ void __launch_bounds__(256, 1)
moe_fused_kernel(const float* __restrict__ x,
                 const float* __restrict__ b1,
                 const float* __restrict__ b2,
                 const float* __restrict__ Wg,
                 const float* __restrict__ bg,
                 float* __restrict__ out) {
    extern __shared__ char smem[];
    __half* xhi  = (__half*)(smem + SM_XHI);
    __half* xlo  = (__half*)(smem + SM_XLO);
    __half* wbuf = (__half*)(smem + SM_WBUF);
    float*  wgs  = (float*)(smem + SM_WBUF);   // fp32 Wg reuses wbuf before expert loop
    __half* hg   = (__half*)(smem + SM_HG);
    float*  gl   = (float*)(smem + SM_GL);     // logits then gates (in place)
    float*  b2s  = (float*)(smem + SM_B2);

    const int tid    = threadIdx.x;
    const int wid    = tid >> 5;
    const int lane   = tid & 31;
    const int gid    = lane >> 2;
    const int tg     = lane & 3;
    const int warp_m = wid >> 1;    // 0..3  (m = warp_m*16 .. +15)
    const int warp_n = wid & 1;     // 0..1
    const int m0     = blockIdx.x * M_TILE;

    // ---- load x tile, split into hi/lo fp16 in one pass ----
    {
        const float4* xg = (const float4*)(x + (size_t)m0 * D_DIM);
        for (int i = tid; i < M_TILE * (D_DIM / 4); i += 256) {
            int r  = i >> 7;
            int c4 = i & 127;
            float4 v = xg[r * 128 + c4];
            __half h0 = __float2half_rn(v.x), h1 = __float2half_rn(v.y);
            __half h2 = __float2half_rn(v.z), h3 = __float2half_rn(v.w);
            __half l0 = __float2half_rn(v.x - __half2float(h0));
            __half l1 = __float2half_rn(v.y - __half2float(h1));
            __half l2 = __float2half_rn(v.z - __half2float(h2));
            __half l3 = __float2half_rn(v.w - __half2float(h3));
            __half2 hh0 = __halves2half2(h0, h1), hh1 = __halves2half2(h2, h3);
            __half2 ll0 = __halves2half2(l0, l1), ll1 = __halves2half2(l2, l3);
            *(uint2*)&xhi[r * XP + c4 * 4] = make_uint2(*(unsigned*)&hh0, *(unsigned*)&hh1);
            *(uint2*)&xlo[r * XP + c4 * 4] = make_uint2(*(unsigned*)&ll0, *(unsigned*)&ll1);
        }
    }
    for (int i = tid; i < E_DIM * C_DIM; i += 256) b2s[i] = b2[i];
    for (int i = tid; i < D_DIM * E_DIM; i += 256) wgs[i] = Wg[i];
    __syncthreads();

    // ---- gate logits (fp32 from hi+lo reconstruction) ----
    {
        int row = tid >> 2;
        int e0  = (tid & 3) * 2;
        float s0 = 0.f, s1 = 0.f;
        for (int d = 0; d < D_DIM; d += 4) {
            uint2 vh = *(const uint2*)&xhi[row * XP + d];
            uint2 vl = *(const uint2*)&xlo[row * XP + d];
            float2 fh0 = __half22float2(*(__half2*)&vh.x);
            float2 fh1 = __half22float2(*(__half2*)&vh.y);
            float2 fl0 = __half22float2(*(__half2*)&vl.x);
            float2 fl1 = __half22float2(*(__half2*)&vl.y);
            float x0 = fh0.x + fl0.x, x1 = fh0.y + fl0.y;
            float x2 = fh1.x + fl1.x, x3 = fh1.y + fl1.y;
            float2 w0 = *(const float2*)&wgs[(d + 0) * E_DIM + e0];
            float2 w1 = *(const float2*)&wgs[(d + 1) * E_DIM + e0];
            float2 w2 = *(const float2*)&wgs[(d + 2) * E_DIM + e0];
            float2 w3 = *(const float2*)&wgs[(d + 3) * E_DIM + e0];
            s0 += x0 * w0.x + x1 * w1.x + x2 * w2.x + x3 * w3.x;
            s1 += x0 * w0.y + x1 * w1.y + x2 * w2.y + x3 * w3.y;
        }
        gl[row * E_DIM + e0]     = s0 + bg[e0];
        gl[row * E_DIM + e0 + 1] = s1 + bg[e0 + 1];
    }
    __syncthreads();
    if (tid < M_TILE) {
        float l[8], m = -1e30f;
        #pragma unroll
        for (int e = 0; e < 8; e++) { l[e] = gl[tid * 8 + e]; m = fmaxf(m, l[e]); }
        float s = 0.f;
        #pragma unroll
        for (int e = 0; e < 8; e++) { l[e] = __expf(l[e] - m); s += l[e]; }
        float inv = 1.f / s;
        #pragma unroll
        for (int e = 0; e < 8; e++) gl[tid * 8 + e] = l[e] * inv;
    }
    __syncthreads();

    // ---- per-lane LDSM byte offsets ----
    const unsigned xhi_u  = su(xhi);
    const unsigned xlo_u  = su(xlo);
    const unsigned wbuf_u = su(wbuf);
    const unsigned hg_u   = su(hg);
    // A fragments (x / hg): rows m0..m15 in lanes 0-15, +8 k-cols in lanes 16-31
    const unsigned aoff1 = ((warp_m * 16 + (lane & 15)) * XP  + (lane >> 4) * 8) * 2;
    const unsigned aoff2 = ((warp_m * 16 + (lane & 15)) * HGP + (lane >> 4) * 8) * 2;
    // B fragments x4 (covers 2 n8 tiles, k16): rows n..n+15, +8 k-cols in hi lanes
    const unsigned boff1 = (((lane & 7) + ((lane >> 3) & 1) * 8) * W1P + (lane >> 4) * 8) * 2;
    const unsigned boff2 = (((lane & 7) + ((lane >> 3) & 1) * 8) * W2P + (lane >> 4) * 8) * 2;
    // B fragment x2 (single n8 tile, k16): lanes 0-7 k0, 8-15 k8
    const unsigned boff2s = ((lane & 7) * W2P + ((lane >> 3) & 1) * 8) * 2;

    const int n2base = warp_n * 56;   // GEMM2 col base (C padded to 112)

    float acc2[7][4];
    #pragma unroll
    for (int i = 0; i < 7; i++)
        #pragma unroll
        for (int j = 0; j < 4; j++) acc2[i][j] = 0.f;

    for (int e = 0; e < E_DIM; e++) {
        // ---- GEMM1: h = x @ W1[e]^T-layout, hi/lo split A ----
        float acc1[16][4];
        #pragma unroll
        for (int i = 0; i < 16; i++)
            #pragma unroll
            for (int j = 0; j < 4; j++) acc1[i][j] = 0.f;

        const __half* w1e = g_W1h + (size_t)e * H_DIM * D_DIM;
        for (int kc = 0; kc < D_DIM; kc += KC) {
            // stage W1 chunk: 256 rows(h) x 64(d), k contiguous
            for (int i = tid; i < H_DIM * (KC / 4); i += 256) {
                int r = i >> 4;
                int c = i & 15;
                uint2 v = *(const uint2*)(w1e + r * D_DIM + kc + c * 4);
                *(uint2*)&wbuf[r * W1P + c * 4] = v;
            }
            __syncthreads();
            #pragma unroll
            for (int ks = 0; ks < KC; ks += 16) {
                unsigned ah0, ah1, ah2, ah3, al0, al1, al2, al3;
                ldsm_x4(ah0, ah1, ah2, ah3, xhi_u + aoff1 + (kc + ks) * 2);
                ldsm_x4(al0, al1, al2, al3, xlo_u + aoff1 + (kc + ks) * 2);
                #pragma unroll
                for (int p = 0; p < 8; p++) {
                    unsigned b0, b1r, b2r, b3r;
                    unsigned base = wbuf_u + ((warp_n * 128 + p * 16) * W1P + ks) * 2 + boff1;
                    ldsm_x4(b0, b1r, b2r, b3r, base);
                    mma16816(acc1[2 * p],     ah0, ah1, ah2, ah3, b0,  b2r);
                    mma16816(acc1[2 * p + 1], ah0, ah1, ah2, ah3, b1r, b3r);
                    mma16816(acc1[2 * p],     al0, al1, al2, al3, b0,  b2r);
                    mma16816(acc1[2 * p + 1], al0, al1, al2, al3, b1r, b3r);
                }
            }
            __syncthreads();
        }

        // ---- epilogue: +b1, relu, *gate -> hg (fp16) ----
        {
            const int r0  = warp_m * 16 + gid;
            float ge0 = gl[r0 * 8 + e];
            float ge1 = gl[(r0 + 8) * 8 + e];
            #pragma unroll
            for (int nt = 0; nt < 16; nt++) {
                int col = warp_n * 128 + nt * 8 + tg * 2;
                float2 bb = *(const float2*)&b1[e * H_DIM + col];
                float v0 = fmaxf(acc1[nt][0] + bb.x, 0.f) * ge0;
                float v1 = fmaxf(acc1[nt][1] + bb.y, 0.f) * ge0;
                float v2 = fmaxf(acc1[nt][2] + bb.x, 0.f) * ge1;
                float v3 = fmaxf(acc1[nt][3] + bb.y, 0.f) * ge1;
                *(__half2*)&hg[r0 * HGP + col]       = __floats2half2_rn(v0, v1);
                *(__half2*)&hg[(r0 + 8) * HGP + col] = __floats2half2_rn(v2, v3);
            }
        }

        // ---- stage W2[e]: 112(c,padded) x 256(h) ----
        {
            const __half* w2e = g_W2h + (size_t)e * C_DIM * H_DIM;
            for (int i = tid; i < C_PAD * 32; i += 256) {
                int r = i >> 5;
                int c = i & 31;
                uint4 v;
                if (r < C_DIM) v = *(const uint4*)(w2e + r * H_DIM + c * 8);
                else           v = make_uint4(0u, 0u, 0u, 0u);
                *(uint4*)&wbuf[r * W2P + c * 8] = v;
            }
        }
        __syncthreads();   // hg written by all warps + W2 staged

        // ---- GEMM2: acc2 += hg @ W2[e]^T-layout ----
        #pragma unroll
        for (int ks = 0; ks < H_DIM; ks += 16) {
            unsigned a0, a1, a2r, a3;
            ldsm_x4(a0, a1, a2r, a3, hg_u + aoff2 + ks * 2);
            #pragma unroll
            for (int p = 0; p < 3; p++) {
                unsigned b0, b1r, b2r, b3r;
                unsigned base = wbuf_u + ((n2base + p * 16) * W2P + ks) * 2 + boff2;
                ldsm_x4(b0, b1r, b2r, b3r, base);
                mma16816(acc2[2 * p],     a0, a1, a2r, a3, b0,  b2r);
                mma16816(acc2[2 * p + 1], a0, a1, a2r, a3, b1r, b3r);
            }
            {   // last n8 tile (nt=6)
                unsigned b0, b1r;
                unsigned base = wbuf_u + ((n2base + 48) * W2P + ks) * 2 + boff2s;
                ldsm_x2(b0, b1r, base);
                mma16816(acc2[6], a0, a1, a2r, a3, b0, b1r);
            }
        }
        __syncthreads();   // wbuf + hg reused next expert
    }

    // ---- final store: out = acc2 + sum_e g[e]*b2[e][c] ----
    {
        const int r0 = warp_m * 16 + gid;
        const float* gr0 = &gl[r0 * 8];
        const float* gr1 = &gl[(r0 + 8) * 8];
        #pragma unroll
        for (int nt = 0; nt < 7; nt++) {
            int col = n2base + nt * 8 + tg * 2;
            #pragma unroll
            for (int cc = 0; cc < 2; cc++) {
                int c = col + cc;
                if (c < C_DIM) {
                    float bias0 = 0.f, bias1 = 0.f;
                    #pragma unroll
                    for (int ee = 0; ee < 8; ee++) {
                        float bv = b2s[ee * C_DIM + c];
                        bias0 += gr0[ee] * bv;
                        bias1 += gr1[ee] * bv;
                    }
                    out[(size_t)(m0 + r0) * C_DIM + c]     = acc2[nt][cc] + bias0;
                    out[(size_t)(m0 + r0 + 8) * C_DIM + c] = acc2[nt][2 + cc] + bias1;
                }
            }
        }
    }
}

extern "C" void kernel_launch(void* const* d_in, const int* in_sizes, int n_in,
                              void* d_out, int out_size) {
    (void)in_sizes; (void)n_in; (void)out_size;
    const float* x  = (const float*)d_in[0];
    const float* W1 = (const float*)d_in[1];
    const float* b1 = (const float*)d_in[2];
    const float* W2 = (const float*)d_in[3];
    const float* b2 = (const float*)d_in[4];
    const float* Wg = (const float*)d_in[5];
    const float* bg = (const float*)d_in[6];
    float* out = (float*)d_out;

    cvt_w1_kernel<<<(E_DIM * H_DIM * D_DIM + 255) / 256, 256>>>(W1);
    cvt_w2_kernel<<<(E_DIM * C_DIM * H_DIM + 255) / 256, 256>>>(W2);

    cudaFuncSetAttribute(moe_fused_kernel,
                         cudaFuncAttributeMaxDynamicSharedMemorySize, SMEM_TOTAL);
    moe_fused_kernel<<<B_ROWS / M_TILE, 256, SMEM_TOTAL>>>(x, b1, b2, Wg, bg, out);
}

// round 5
// speedup vs baseline: 1.1651x; 1.1268x over previous
#include <cuda_runtime.h>
#include <cuda_fp16.h>
#include <cstdint>

// Problem constants
#define B_ROWS 65536
#define D_DIM  512
#define C_DIM  101
#define E_DIM  8
#define H_DIM  256

#define M_TILE 64
#define KC     32        // GEMM1 K-chunk (cp.async double-buffered)
#define NCH    16        // 512/32 chunks
#define XP     520       // fp16 pitch xhi/xlo (1040B; %128B=16 -> LDSM conflict-free)
#define W1P    40        // fp16 pitch W1 chunk (80B; %128=80, 8-row LDSM distinct)
#define W2P    72        // fp16 pitch W2 quarter (144B; %128=16)
#define HGP    264       // fp16 pitch hidden tile (528B; %128=16)
#define WBUF_SZ 20480    // one staging buffer (fits 256x40 or 112x72 halfs)

// Shared memory layout (bytes)
#define SM_XHI 0         // 64*520*2 = 66560
#define SM_XLO 66560     // 66560
#define SM_WB  133120    // 2 x 20480 = 40960 (W1 chunks / W2 quarters)
#define SM_HG  174080    // 64*264*2 = 33792 (also Wg fp32 staging pre-loop)
#define SM_GL  207872    // 64*8*4 = 2048
#define SM_B2  209920    // 808*4 = 3232
#define SMEM_TOTAL 213152

// fp16 weight scratch (converted+transposed once per launch; graph-deterministic)
__device__ __align__(16) __half g_W1h[E_DIM * H_DIM * D_DIM];  // [e][h][d]
__device__ __align__(16) __half g_W2h[E_DIM * C_DIM * H_DIM];  // [e][c][h]

__global__ void cvt_w1_kernel(const float* __restrict__ W1) {
    int idx = blockIdx.x * blockDim.x + threadIdx.x;
    if (idx >= E_DIM * H_DIM * D_DIM) return;
    int d = idx & (D_DIM - 1);
    int h = (idx >> 9) & (H_DIM - 1);
    int e = idx >> 17;
    g_W1h[idx] = __float2half_rn(W1[(e * D_DIM + d) * H_DIM + h]);
}

__global__ void cvt_w2_kernel(const float* __restrict__ W2) {
    int idx = blockIdx.x * blockDim.x + threadIdx.x;
    if (idx >= E_DIM * C_DIM * H_DIM) return;
    int h = idx & (H_DIM - 1);
    int t = idx >> 8;
    int c = t % C_DIM;
    int e = t / C_DIM;
    g_W2h[idx] = __float2half_rn(W2[(e * H_DIM + h) * C_DIM + c]);
}

// ---------------- PTX helpers ----------------
__device__ __forceinline__ void mma16816(float* c,
                                         unsigned a0, unsigned a1, unsigned a2, unsigned a3,
                                         unsigned b0, unsigned b1) {
    asm volatile(
        "mma.sync.aligned.m16n8k16.row.col.f32.f16.f16.f32 "
        "{%0,%1,%2,%3}, {%4,%5,%6,%7}, {%8,%9}, {%0,%1,%2,%3};\n"
        : "+f"(c[0]), "+f"(c[1]), "+f"(c[2]), "+f"(c[3])
        : "r"(a0), "r"(a1), "r"(a2), "r"(a3), "r"(b0), "r"(b1));
}
__device__ __forceinline__ void ldsm_x4(unsigned& r0, unsigned& r1, unsigned& r2,
                                        unsigned& r3, unsigned addr) {
    asm volatile("ldmatrix.sync.aligned.m8n8.x4.shared.b16 {%0,%1,%2,%3}, [%4];\n"
                 : "=r"(r0), "=r"(r1), "=r"(r2), "=r"(r3) : "r"(addr));
}
__device__ __forceinline__ void ldsm_x2(unsigned& r0, unsigned& r1, unsigned addr) {
    asm volatile("ldmatrix.sync.aligned.m8n8.x2.shared.b16 {%0,%1}, [%2];\n"
                 : "=r"(r0), "=r"(r1) : "r"(addr));
}
__device__ __forceinline__ unsigned su(const void* p) {
    return (unsigned)__cvta_generic_to_shared(p);
}
__device__ __forceinline__ void cpa16(unsigned dst, const void* src) {
    asm volatile("cp.async.cg.shared.global [%0], [%1], 16;\n" :: "r"(dst), "l"(src));
}
__device__ __forceinline__ void cpa_commit() {
    asm volatile("cp.async.commit_group;\n" ::: "memory");
}
__device__ __forceinline__ void cpa_wait1() {
    asm volatile("cp.async.wait_group 1;\n" ::: "memory");
}
__device__ __forceinline__ void cpa_wait0() {
    asm volatile("cp.async.wait_group 0;\n" ::: "memory");
}

// ---------------- staging (cp.async) ----------------
__device__ __forceinline__ void stage_w1(unsigned wb_u, const __half* w1e,
                                         int kc, int buf, int tid) {
    unsigned dst = wb_u + buf * WBUF_SZ;
    const __half* src = w1e + kc * KC;
    #pragma unroll
    for (int it = 0; it < 4; it++) {           // 256 rows x 4 x 16B
        int i = tid + it * 256;
        int r = i >> 2, s = i & 3;
        cpa16(dst + r * (W1P * 2) + s * 16, src + (size_t)r * D_DIM + s * 8);
    }
}
__device__ __forceinline__ void stage_w2(unsigned wb_u, const __half* w2e,
                                         int q, int buf, int tid) {
    unsigned dst = wb_u + buf * WBUF_SZ;
    const __half* src = w2e + q * 64;
    #pragma unroll
    for (int it = 0; it < 4; it++) {           // 101 rows x 8 x 16B (pad rows skipped)
        int i = tid + it * 256;
        int r = i >> 3, s = i & 7;
        if (i < 896 && r < C_DIM)
            cpa16(dst + r * (W2P * 2) + s * 16, src + (size_t)r * H_DIM + s * 8);
    }
}

__global__ void __launch_bounds__(256, 1)
moe_fused_kernel(const float* __restrict__ x,
                 const float* __restrict__ b1,
                 const float* __restrict__ b2,
                 const float* __restrict__ Wg,
                 const float* __restrict__ bg,
                 float* __restrict__ out) {
    extern __shared__ char smem[];
    __half* xhi = (__half*)(smem + SM_XHI);
    __half* xlo = (__half*)(smem + SM_XLO);
    __half* hg  = (__half*)(smem + SM_HG);
    float*  wgs = (float*)(smem + SM_HG);     // Wg fp32 staging, pre-loop only
    float*  gl  = (float*)(smem + SM_GL);
    float*  b2s = (float*)(smem + SM_B2);

    const int tid    = threadIdx.x;
    const int wid    = tid >> 5;
    const int lane   = tid & 31;
    const int gid    = lane >> 2;
    const int tg     = lane & 3;
    const int warp_m = wid >> 1;    // 0..3
    const int warp_n = wid & 1;     // 0..1
    const int m0     = blockIdx.x * M_TILE;

    const unsigned xhi_u = su(xhi);
    const unsigned xlo_u = su(xlo);
    const unsigned wb_u  = su(smem + SM_WB);
    const unsigned hg_u  = su(hg);

    // ---- kick off W1 expert-0 chunk 0/1 staging immediately ----
    stage_w1(wb_u, g_W1h, 0, 0, tid); cpa_commit();
    stage_w1(wb_u, g_W1h, 1, 1, tid); cpa_commit();

    // ---- load x tile, split hi/lo fp16 (overlaps with cp.async above) ----
    {
        const float4* xg = (const float4*)(x + (size_t)m0 * D_DIM);
        #pragma unroll 4
        for (int it = 0; it < 32; it++) {
            int i  = tid + it * 256;
            int r  = i >> 7, c4 = i & 127;
            float4 v = xg[r * 128 + c4];
            __half h0 = __float2half_rn(v.x), h1 = __float2half_rn(v.y);
            __half h2 = __float2half_rn(v.z), h3 = __float2half_rn(v.w);
            __half l0 = __float2half_rn(v.x - __half2float(h0));
            __half l1 = __float2half_rn(v.y - __half2float(h1));
            __half l2 = __float2half_rn(v.z - __half2float(h2));
            __half l3 = __float2half_rn(v.w - __half2float(h3));
            __half2 hh0 = __halves2half2(h0, h1), hh1 = __halves2half2(h2, h3);
            __half2 ll0 = __halves2half2(l0, l1), ll1 = __halves2half2(l2, l3);
            *(uint2*)&xhi[r * XP + c4 * 4] = make_uint2(*(unsigned*)&hh0, *(unsigned*)&hh1);
            *(uint2*)&xlo[r * XP + c4 * 4] = make_uint2(*(unsigned*)&ll0, *(unsigned*)&ll1);
        }
    }
    for (int i = tid; i < E_DIM * C_DIM; i += 256) b2s[i] = b2[i];
    for (int i = tid; i < D_DIM * E_DIM; i += 256) wgs[i] = Wg[i];
    __syncthreads();

    // ---- gate logits (fp32 via hi+lo reconstruction) + softmax ----
    {
        int row = tid >> 2;
        int e0  = (tid & 3) * 2;
        float s0 = 0.f, s1 = 0.f;
        for (int d = 0; d < D_DIM; d += 4) {
            uint2 vh = *(const uint2*)&xhi[row * XP + d];
            uint2 vl = *(const uint2*)&xlo[row * XP + d];
            float2 fh0 = __half22float2(*(__half2*)&vh.x);
            float2 fh1 = __half22float2(*(__half2*)&vh.y);
            float2 fl0 = __half22float2(*(__half2*)&vl.x);
            float2 fl1 = __half22float2(*(__half2*)&vl.y);
            float x0 = fh0.x + fl0.x, x1 = fh0.y + fl0.y;
            float x2 = fh1.x + fl1.x, x3 = fh1.y + fl1.y;
            float2 w0 = *(const float2*)&wgs[(d + 0) * E_DIM + e0];
            float2 w1 = *(const float2*)&wgs[(d + 1) * E_DIM + e0];
            float2 w2 = *(const float2*)&wgs[(d + 2) * E_DIM + e0];
            float2 w3 = *(const float2*)&wgs[(d + 3) * E_DIM + e0];
            s0 += x0 * w0.x + x1 * w1.x + x2 * w2.x + x3 * w3.x;
            s1 += x0 * w0.y + x1 * w1.y + x2 * w2.y + x3 * w3.y;
        }
        gl[row * E_DIM + e0]     = s0 + bg[e0];
        gl[row * E_DIM + e0 + 1] = s1 + bg[e0 + 1];
    }
    __syncthreads();
    if (tid < M_TILE) {
        float l[8], m = -1e30f;
        #pragma unroll
        for (int e = 0; e < 8; e++) { l[e] = gl[tid * 8 + e]; m = fmaxf(m, l[e]); }
        float s = 0.f;
        #pragma unroll
        for (int e = 0; e < 8; e++) { l[e] = __expf(l[e] - m); s += l[e]; }
        float inv = 1.f / s;
        #pragma unroll
        for (int e = 0; e < 8; e++) gl[tid * 8 + e] = l[e] * inv;
    }
    // NOTE: hg/wgs alias — gates done before first epilogue writes hg; sync in loop.

    // ---- per-lane LDSM byte offsets ----
    const unsigned aoff1 = ((warp_m * 16 + (lane & 15)) * XP  + (lane >> 4) * 8) * 2;
    const unsigned aoff2 = ((warp_m * 16 + (lane & 15)) * HGP + (lane >> 4) * 8) * 2;
    const unsigned boff1 = (((lane & 7) + ((lane >> 3) & 1) * 8) * W1P + (lane >> 4) * 8) * 2;
    const unsigned boff2 = (((lane & 7) + ((lane >> 3) & 1) * 8) * W2P + (lane >> 4) * 8) * 2;
    const unsigned boff2s = ((lane & 7) * W2P + ((lane >> 3) & 1) * 8) * 2;
    const int n2base = warp_n * 56;

    float acc2[7][4];
    #pragma unroll
    for (int i = 0; i < 7; i++)
        #pragma unroll
        for (int j = 0; j < 4; j++) acc2[i][j] = 0.f;

    for (int e = 0; e < E_DIM; e++) {
        const __half* w1e = g_W1h + (size_t)e * H_DIM * D_DIM;
        const __half* w2e = g_W2h + (size_t)e * C_DIM * H_DIM;
        const __half* w1n = g_W1h + (size_t)(e + 1) * H_DIM * D_DIM;

        float acc1[16][4];
        #pragma unroll
        for (int i = 0; i < 16; i++)
            #pragma unroll
            for (int j = 0; j < 4; j++) acc1[i][j] = 0.f;

        // ---- GEMM1: 16 chunks of K=32, 2-deep cp.async pipeline ----
        for (int kc = 0; kc < NCH; kc++) {
            cpa_wait1();
            __syncthreads();                    // chunk kc ready everywhere
            const int buf = kc & 1;
            const unsigned bbase0 = wb_u + buf * WBUF_SZ + boff1;
            #pragma unroll
            for (int ks = 0; ks < KC; ks += 16) {
                unsigned ah0, ah1, ah2, ah3, al0, al1, al2, al3;
                ldsm_x4(ah0, ah1, ah2, ah3, xhi_u + aoff1 + (kc * KC + ks) * 2);
                ldsm_x4(al0, al1, al2, al3, xlo_u + aoff1 + (kc * KC + ks) * 2);
                #pragma unroll
                for (int p = 0; p < 8; p++) {
                    unsigned b0, b1r, b2r, b3r;
                    unsigned base = bbase0 + ((warp_n * 128 + p * 16) * W1P + ks) * 2;
                    ldsm_x4(b0, b1r, b2r, b3r, base);
                    mma16816(acc1[2 * p],     ah0, ah1, ah2, ah3, b0,  b2r);
                    mma16816(acc1[2 * p + 1], ah0, ah1, ah2, ah3, b1r, b3r);
                    mma16816(acc1[2 * p],     al0, al1, al2, al3, b0,  b2r);
                    mma16816(acc1[2 * p + 1], al0, al1, al2, al3, b1r, b3r);
                }
            }
            __syncthreads();                    // all warps done reading buf
            int nxt = kc + 2;
            if (nxt < NCH) { stage_w1(wb_u, w1e, nxt, buf, tid); cpa_commit(); }
            else           { stage_w2(wb_u, w2e, nxt - NCH, buf, tid); cpa_commit(); }
        }

        // ---- epilogue: +b1, relu, *gate -> hg (overlaps W2 q0/q1 staging) ----
        {
            const int r0  = warp_m * 16 + gid;
            float ge0 = gl[r0 * 8 + e];
            float ge1 = gl[(r0 + 8) * 8 + e];
            #pragma unroll
            for (int nt = 0; nt < 16; nt++) {
                int col = warp_n * 128 + nt * 8 + tg * 2;
                float2 bb = *(const float2*)&b1[e * H_DIM + col];
                float v0 = fmaxf(acc1[nt][0] + bb.x, 0.f) * ge0;
                float v1 = fmaxf(acc1[nt][1] + bb.y, 0.f) * ge0;
                float v2 = fmaxf(acc1[nt][2] + bb.x, 0.f) * ge1;
                float v3 = fmaxf(acc1[nt][3] + bb.y, 0.f) * ge1;
                *(__half2*)&hg[r0 * HGP + col]       = __floats2half2_rn(v0, v1);
                *(__half2*)&hg[(r0 + 8) * HGP + col] = __floats2half2_rn(v2, v3);
            }
        }
        __syncthreads();                        // hg complete (cross-warp A reads)

        // ---- GEMM2: 4 quarters of K=64, same 2-buffer pipeline ----
        for (int q = 0; q < 4; q++) {
            if (q < 3 || e < E_DIM - 1) cpa_wait1(); else cpa_wait0();
            __syncthreads();
            const int buf = q & 1;
            const unsigned bb2 = wb_u + buf * WBUF_SZ;
            #pragma unroll
            for (int ks = 0; ks < 64; ks += 16) {
                unsigned a0, a1, a2r, a3;
                ldsm_x4(a0, a1, a2r, a3, hg_u + aoff2 + (q * 64 + ks) * 2);
                #pragma unroll
                for (int p = 0; p < 3; p++) {
                    unsigned b0, b1r, b2r, b3r;
                    unsigned base = bb2 + ((n2base + p * 16) * W2P + ks) * 2 + boff2;
                    ldsm_x4(b0, b1r, b2r, b3r, base);
                    mma16816(acc2[2 * p],     a0, a1, a2r, a3, b0,  b2r);
                    mma16816(acc2[2 * p + 1], a0, a1, a2r, a3, b1r, b3r);
                }
                {
                    unsigned b0, b1r;
                    unsigned base = bb2 + ((n2base + 48) * W2P + ks) * 2 + boff2s;
                    ldsm_x2(b0, b1r, base);
                    mma16816(acc2[6], a0, a1, a2r, a3, b0, b1r);
                }
            }
            __syncthreads();
            int nq = q + 2;
            if (nq < 4)               { stage_w2(wb_u, w2e, nq, buf, tid); cpa_commit(); }
            else if (e + 1 < E_DIM)   { stage_w1(wb_u, w1n, nq - 4, buf, tid); cpa_commit(); }
        }
    }

    // ---- final store: out = acc2 + sum_e g[e]*b2[e][c] ----
    {
        const int r0 = warp_m * 16 + gid;
        const float* gr0 = &gl[r0 * 8];
        const float* gr1 = &gl[(r0 + 8) * 8];
        #pragma unroll
        for (int nt = 0; nt < 7; nt++) {
            int col = n2base + nt * 8 + tg * 2;
            #pragma unroll
            for (int cc = 0; cc < 2; cc++) {
                int c = col + cc;
                if (c < C_DIM) {
                    float bias0 = 0.f, bias1 = 0.f;
                    #pragma unroll
                    for (int ee = 0; ee < 8; ee++) {
                        float bv = b2s[ee * C_DIM + c];
                        bias0 += gr0[ee] * bv;
                        bias1 += gr1[ee] * bv;
                    }
                    out[(size_t)(m0 + r0) * C_DIM + c]     = acc2[nt][cc] + bias0;
                    out[(size_t)(m0 + r0 + 8) * C_DIM + c] = acc2[nt][2 + cc] + bias1;
                }
            }
        }
    }
}

extern "C" void kernel_launch(void* const* d_in, const int* in_sizes, int n_in,
                              void* d_out, int out_size) {
    (void)in_sizes; (void)n_in; (void)out_size;
    const float* x  = (const float*)d_in[0];
    const float* W1 = (const float*)d_in[1];
    const float* b1 = (const float*)d_in[2];
    const float* W2 = (const float*)d_in[3];
    const float* b2 = (const float*)d_in[4];
    const float* Wg = (const float*)d_in[5];
    const float* bg = (const float*)d_in[6];
    float* out = (float*)d_out;

    cvt_w1_kernel<<<(E_DIM * H_DIM * D_DIM + 255) / 256, 256>>>(W1);
    cvt_w2_kernel<<<(E_DIM * C_DIM * H_DIM + 255) / 256, 256>>>(W2);

    cudaFuncSetAttribute(moe_fused_kernel,
                         cudaFuncAttributeMaxDynamicSharedMemorySize, SMEM_TOTAL);
    moe_fused_kernel<<<B_ROWS / M_TILE, 256, SMEM_TOTAL>>>(x, b1, b2, Wg, bg, out);
}

// round 6
// speedup vs baseline: 1.6122x; 1.3838x over previous
#include <cuda_runtime.h>
#include <cuda_fp16.h>
#include <cstdint>

// Problem constants
#define B_ROWS 65536
#define D_DIM  512
#define C_DIM  101
#define E_DIM  8
#define H_DIM  256

#define M_TILE 64
#define KC     32        // GEMM1 K-chunk (cp.async double-buffered)
#define NCH    16        // 512/32 chunks
#define XP     520       // fp16 pitch xhi/xlo (1040B; %128B=16 -> LDSM conflict-free)
#define W1P    40        // fp16 pitch W1 chunk (80B; %128=80, 8-row LDSM distinct)
#define W2P    72        // fp16 pitch W2 quarter (144B; %128=16)
#define HGP    264       // fp16 pitch hidden tile (528B; %128=16)
#define WBUF_SZ 20480    // one staging buffer (fits 256x40 or 112x72 halfs)

// Shared memory layout (bytes)
#define SM_XHI 0         // 64*520*2 = 66560
#define SM_XLO 66560     // 66560 (gate-logit accuracy only)
#define SM_WB  133120    // 2 x 20480 = 40960 (W1 chunks / W2 quarters)
#define SM_HG  174080    // 64*264*2 = 33792 (also Wg fp32 staging pre-loop)
#define SM_GL  207872    // 64*8*4 = 2048
#define SM_B2  209920    // 808*4 = 3232
#define SMEM_TOTAL 213152

// fp16 weight scratch (converted+transposed once per launch; graph-deterministic)
__device__ __align__(16) __half g_W1h[E_DIM * H_DIM * D_DIM];  // [e][h][d]
__device__ __align__(16) __half g_W2h[E_DIM * C_DIM * H_DIM];  // [e][c][h]

__global__ void cvt_w1_kernel(const float* __restrict__ W1) {
    int idx = blockIdx.x * blockDim.x + threadIdx.x;
    if (idx >= E_DIM * H_DIM * D_DIM) return;
    int d = idx & (D_DIM - 1);
    int h = (idx >> 9) & (H_DIM - 1);
    int e = idx >> 17;
    g_W1h[idx] = __float2half_rn(W1[(e * D_DIM + d) * H_DIM + h]);
}

__global__ void cvt_w2_kernel(const float* __restrict__ W2) {
    int idx = blockIdx.x * blockDim.x + threadIdx.x;
    if (idx >= E_DIM * C_DIM * H_DIM) return;
    int h = idx & (H_DIM - 1);
    int t = idx >> 8;
    int c = t % C_DIM;
    int e = t / C_DIM;
    g_W2h[idx] = __float2half_rn(W2[(e * H_DIM + h) * C_DIM + c]);
}

// ---------------- PTX helpers ----------------
__device__ __forceinline__ void mma16816(float* c,
                                         unsigned a0, unsigned a1, unsigned a2, unsigned a3,
                                         unsigned b0, unsigned b1) {
    asm volatile(
        "mma.sync.aligned.m16n8k16.row.col.f32.f16.f16.f32 "
        "{%0,%1,%2,%3}, {%4,%5,%6,%7}, {%8,%9}, {%0,%1,%2,%3};\n"
        : "+f"(c[0]), "+f"(c[1]), "+f"(c[2]), "+f"(c[3])
        : "r"(a0), "r"(a1), "r"(a2), "r"(a3), "r"(b0), "r"(b1));
}
__device__ __forceinline__ void ldsm_x4(unsigned& r0, unsigned& r1, unsigned& r2,
                                        unsigned& r3, unsigned addr) {
    asm volatile("ldmatrix.sync.aligned.m8n8.x4.shared.b16 {%0,%1,%2,%3}, [%4];\n"
                 : "=r"(r0), "=r"(r1), "=r"(r2), "=r"(r3) : "r"(addr));
}
__device__ __forceinline__ void ldsm_x2(unsigned& r0, unsigned& r1, unsigned addr) {
    asm volatile("ldmatrix.sync.aligned.m8n8.x2.shared.b16 {%0,%1}, [%2];\n"
                 : "=r"(r0), "=r"(r1) : "r"(addr));
}
__device__ __forceinline__ unsigned su(const void* p) {
    return (unsigned)__cvta_generic_to_shared(p);
}
__device__ __forceinline__ void cpa16(unsigned dst, const void* src) {
    asm volatile("cp.async.cg.shared.global [%0], [%1], 16;\n" :: "r"(dst), "l"(src));
}
__device__ __forceinline__ void cpa_commit() {
    asm volatile("cp.async.commit_group;\n" ::: "memory");
}
__device__ __forceinline__ void cpa_wait1() {
    asm volatile("cp.async.wait_group 1;\n" ::: "memory");
}
__device__ __forceinline__ void cpa_wait0() {
    asm volatile("cp.async.wait_group 0;\n" ::: "memory");
}

// ---------------- staging (cp.async) ----------------
__device__ __forceinline__ void stage_w1(unsigned wb_u, const __half* w1e,
                                         int kc, int buf, int tid) {
    unsigned dst = wb_u + buf * WBUF_SZ;
    const __half* src = w1e + kc * KC;
    #pragma unroll
    for (int it = 0; it < 4; it++) {           // 256 rows x 4 x 16B
        int i = tid + it * 256;
        int r = i >> 2, s = i & 3;
        cpa16(dst + r * (W1P * 2) + s * 16, src + (size_t)r * D_DIM + s * 8);
    }
}
__device__ __forceinline__ void stage_w2(unsigned wb_u, const __half* w2e,
                                         int q, int buf, int tid) {
    unsigned dst = wb_u + buf * WBUF_SZ;
    const __half* src = w2e + q * 64;
    #pragma unroll
    for (int it = 0; it < 4; it++) {           // 101 rows x 8 x 16B (pad rows skipped)
        int i = tid + it * 256;
        int r = i >> 3, s = i & 7;
        if (i < 896 && r < C_DIM)
            cpa16(dst + r * (W2P * 2) + s * 16, src + (size_t)r * H_DIM + s * 8);
    }
}

__global__ void __launch_bounds__(256, 1)
moe_fused_kernel(const float* __restrict__ x,
                 const float* __restrict__ b1,
                 const float* __restrict__ b2,
                 const float* __restrict__ Wg,
                 const float* __restrict__ bg,
                 float* __restrict__ out) {
    extern __shared__ char smem[];
    __half* xhi = (__half*)(smem + SM_XHI);
    __half* xlo = (__half*)(smem + SM_XLO);
    __half* hg  = (__half*)(smem + SM_HG);
    float*  wgs = (float*)(smem + SM_HG);     // Wg fp32 staging, pre-loop only
    float*  gl  = (float*)(smem + SM_GL);
    float*  b2s = (float*)(smem + SM_B2);

    const int tid    = threadIdx.x;
    const int wid    = tid >> 5;
    const int lane   = tid & 31;
    const int gid    = lane >> 2;
    const int tg     = lane & 3;
    const int warp_m = wid >> 1;    // 0..3
    const int warp_n = wid & 1;     // 0..1
    const int m0     = blockIdx.x * M_TILE;

    const unsigned xhi_u = su(xhi);
    const unsigned wb_u  = su(smem + SM_WB);
    const unsigned hg_u  = su(hg);

    // ---- kick off W1 expert-0 chunk 0/1 staging immediately ----
    stage_w1(wb_u, g_W1h, 0, 0, tid); cpa_commit();
    stage_w1(wb_u, g_W1h, 1, 1, tid); cpa_commit();

    // ---- load x tile, split hi/lo fp16 (overlaps with cp.async above) ----
    // xhi feeds GEMM1 A; xlo is kept ONLY for fp32-accurate gate logits.
    {
        const float4* xg = (const float4*)(x + (size_t)m0 * D_DIM);
        #pragma unroll 4
        for (int it = 0; it < 32; it++) {
            int i  = tid + it * 256;
            int r  = i >> 7, c4 = i & 127;
            float4 v = xg[r * 128 + c4];
            __half h0 = __float2half_rn(v.x), h1 = __float2half_rn(v.y);
            __half h2 = __float2half_rn(v.z), h3 = __float2half_rn(v.w);
            __half l0 = __float2half_rn(v.x - __half2float(h0));
            __half l1 = __float2half_rn(v.y - __half2float(h1));
            __half l2 = __float2half_rn(v.z - __half2float(h2));
            __half l3 = __float2half_rn(v.w - __half2float(h3));
            __half2 hh0 = __halves2half2(h0, h1), hh1 = __halves2half2(h2, h3);
            __half2 ll0 = __halves2half2(l0, l1), ll1 = __halves2half2(l2, l3);
            *(uint2*)&xhi[r * XP + c4 * 4] = make_uint2(*(unsigned*)&hh0, *(unsigned*)&hh1);
            *(uint2*)&xlo[r * XP + c4 * 4] = make_uint2(*(unsigned*)&ll0, *(unsigned*)&ll1);
        }
    }
    for (int i = tid; i < E_DIM * C_DIM; i += 256) b2s[i] = b2[i];
    for (int i = tid; i < D_DIM * E_DIM; i += 256) wgs[i] = Wg[i];
    __syncthreads();

    // ---- gate logits (fp32 via hi+lo reconstruction) + softmax ----
    {
        int row = tid >> 2;
        int e0  = (tid & 3) * 2;
        float s0 = 0.f, s1 = 0.f;
        for (int d = 0; d < D_DIM; d += 4) {
            uint2 vh = *(const uint2*)&xhi[row * XP + d];
            uint2 vl = *(const uint2*)&xlo[row * XP + d];
            float2 fh0 = __half22float2(*(__half2*)&vh.x);
            float2 fh1 = __half22float2(*(__half2*)&vh.y);
            float2 fl0 = __half22float2(*(__half2*)&vl.x);
            float2 fl1 = __half22float2(*(__half2*)&vl.y);
            float x0 = fh0.x + fl0.x, x1 = fh0.y + fl0.y;
            float x2 = fh1.x + fl1.x, x3 = fh1.y + fl1.y;
            float2 w0 = *(const float2*)&wgs[(d + 0) * E_DIM + e0];
            float2 w1 = *(const float2*)&wgs[(d + 1) * E_DIM + e0];
            float2 w2 = *(const float2*)&wgs[(d + 2) * E_DIM + e0];
            float2 w3 = *(const float2*)&wgs[(d + 3) * E_DIM + e0];
            s0 += x0 * w0.x + x1 * w1.x + x2 * w2.x + x3 * w3.x;
            s1 += x0 * w0.y + x1 * w1.y + x2 * w2.y + x3 * w3.y;
        }
        gl[row * E_DIM + e0]     = s0 + bg[e0];
        gl[row * E_DIM + e0 + 1] = s1 + bg[e0 + 1];
    }
    __syncthreads();
    if (tid < M_TILE) {
        float l[8], m = -1e30f;
        #pragma unroll
        for (int e = 0; e < 8; e++) { l[e] = gl[tid * 8 + e]; m = fmaxf(m, l[e]); }
        float s = 0.f;
        #pragma unroll
        for (int e = 0; e < 8; e++) { l[e] = __expf(l[e] - m); s += l[e]; }
        float inv = 1.f / s;
        #pragma unroll
        for (int e = 0; e < 8; e++) gl[tid * 8 + e] = l[e] * inv;
    }
    // NOTE: hg/wgs alias — gates done before first epilogue writes hg; sync in loop.

    // ---- per-lane LDSM byte offsets ----
    const unsigned aoff1 = ((warp_m * 16 + (lane & 15)) * XP  + (lane >> 4) * 8) * 2;
    const unsigned aoff2 = ((warp_m * 16 + (lane & 15)) * HGP + (lane >> 4) * 8) * 2;
    const unsigned boff1 = (((lane & 7) + ((lane >> 3) & 1) * 8) * W1P + (lane >> 4) * 8) * 2;
    const unsigned boff2 = (((lane & 7) + ((lane >> 3) & 1) * 8) * W2P + (lane >> 4) * 8) * 2;
    const unsigned boff2s = ((lane & 7) * W2P + ((lane >> 3) & 1) * 8) * 2;
    const int n2base = warp_n * 56;

    float acc2[7][4];
    #pragma unroll
    for (int i = 0; i < 7; i++)
        #pragma unroll
        for (int j = 0; j < 4; j++) acc2[i][j] = 0.f;

    for (int e = 0; e < E_DIM; e++) {
        const __half* w1e = g_W1h + (size_t)e * H_DIM * D_DIM;
        const __half* w2e = g_W2h + (size_t)e * C_DIM * H_DIM;
        const __half* w1n = g_W1h + (size_t)(e + 1) * H_DIM * D_DIM;

        float acc1[16][4];
        #pragma unroll
        for (int i = 0; i < 16; i++)
            #pragma unroll
            for (int j = 0; j < 4; j++) acc1[i][j] = 0.f;

        // ---- GEMM1: 16 chunks of K=32, 2-deep cp.async pipeline (hi-only A) ----
        for (int kc = 0; kc < NCH; kc++) {
            cpa_wait1();
            __syncthreads();                    // chunk kc ready everywhere
            const int buf = kc & 1;
            const unsigned bbase0 = wb_u + buf * WBUF_SZ + boff1;
            #pragma unroll
            for (int ks = 0; ks < KC; ks += 16) {
                unsigned ah0, ah1, ah2, ah3;
                ldsm_x4(ah0, ah1, ah2, ah3, xhi_u + aoff1 + (kc * KC + ks) * 2);
                #pragma unroll
                for (int p = 0; p < 8; p++) {
                    unsigned b0, b1r, b2r, b3r;
                    unsigned base = bbase0 + ((warp_n * 128 + p * 16) * W1P + ks) * 2;
                    ldsm_x4(b0, b1r, b2r, b3r, base);
                    mma16816(acc1[2 * p],     ah0, ah1, ah2, ah3, b0,  b2r);
                    mma16816(acc1[2 * p + 1], ah0, ah1, ah2, ah3, b1r, b3r);
                }
            }
            __syncthreads();                    // all warps done reading buf
            int nxt = kc + 2;
            if (nxt < NCH) { stage_w1(wb_u, w1e, nxt, buf, tid); cpa_commit(); }
            else           { stage_w2(wb_u, w2e, nxt - NCH, buf, tid); cpa_commit(); }
        }

        // ---- epilogue: +b1, relu, *gate -> hg (overlaps W2 q0/q1 staging) ----
        {
            const int r0  = warp_m * 16 + gid;
            float ge0 = gl[r0 * 8 + e];
            float ge1 = gl[(r0 + 8) * 8 + e];
            #pragma unroll
            for (int nt = 0; nt < 16; nt++) {
                int col = warp_n * 128 + nt * 8 + tg * 2;
                float2 bb = *(const float2*)&b1[e * H_DIM + col];
                float v0 = fmaxf(acc1[nt][0] + bb.x, 0.f) * ge0;
                float v1 = fmaxf(acc1[nt][1] + bb.y, 0.f) * ge0;
                float v2 = fmaxf(acc1[nt][2] + bb.x, 0.f) * ge1;
                float v3 = fmaxf(acc1[nt][3] + bb.y, 0.f) * ge1;
                *(__half2*)&hg[r0 * HGP + col]       = __floats2half2_rn(v0, v1);
                *(__half2*)&hg[(r0 + 8) * HGP + col] = __floats2half2_rn(v2, v3);
            }
        }
        __syncthreads();                        // hg complete (cross-warp A reads)

        // ---- GEMM2: 4 quarters of K=64, same 2-buffer pipeline ----
        for (int q = 0; q < 4; q++) {
            if (q < 3 || e < E_DIM - 1) cpa_wait1(); else cpa_wait0();
            __syncthreads();
            const int buf = q & 1;
            const unsigned bb2 = wb_u + buf * WBUF_SZ;
            #pragma unroll
            for (int ks = 0; ks < 64; ks += 16) {
                unsigned a0, a1, a2r, a3;
                ldsm_x4(a0, a1, a2r, a3, hg_u + aoff2 + (q * 64 + ks) * 2);
                #pragma unroll
                for (int p = 0; p < 3; p++) {
                    unsigned b0, b1r, b2r, b3r;
                    unsigned base = bb2 + ((n2base + p * 16) * W2P + ks) * 2 + boff2;
                    ldsm_x4(b0, b1r, b2r, b3r, base);
                    mma16816(acc2[2 * p],     a0, a1, a2r, a3, b0,  b2r);
                    mma16816(acc2[2 * p + 1], a0, a1, a2r, a3, b1r, b3r);
                }
                {
                    unsigned b0, b1r;
                    unsigned base = bb2 + ((n2base + 48) * W2P + ks) * 2 + boff2s;
                    ldsm_x2(b0, b1r, base);
                    mma16816(acc2[6], a0, a1, a2r, a3, b0, b1r);
                }
            }
            __syncthreads();
            int nq = q + 2;
            if (nq < 4)               { stage_w2(wb_u, w2e, nq, buf, tid); cpa_commit(); }
            else if (e + 1 < E_DIM)   { stage_w1(wb_u, w1n, nq - 4, buf, tid); cpa_commit(); }
        }
    }

    // ---- final store: out = acc2 + sum_e g[e]*b2[e][c] ----
    {
        const int r0 = warp_m * 16 + gid;
        const float* gr0 = &gl[r0 * 8];
        const float* gr1 = &gl[(r0 + 8) * 8];
        #pragma unroll
        for (int nt = 0; nt < 7; nt++) {
            int col = n2base + nt * 8 + tg * 2;
            #pragma unroll
            for (int cc = 0; cc < 2; cc++) {
                int c = col + cc;
                if (c < C_DIM) {
                    float bias0 = 0.f, bias1 = 0.f;
                    #pragma unroll
                    for (int ee = 0; ee < 8; ee++) {
                        float bv = b2s[ee * C_DIM + c];
                        bias0 += gr0[ee] * bv;
                        bias1 += gr1[ee] * bv;
                    }
                    out[(size_t)(m0 + r0) * C_DIM + c]     = acc2[nt][cc] + bias0;
                    out[(size_t)(m0 + r0 + 8) * C_DIM + c] = acc2[nt][2 + cc] + bias1;
                }
            }
        }
    }
}

extern "C" void kernel_launch(void* const* d_in, const int* in_sizes, int n_in,
                              void* d_out, int out_size) {
    (void)in_sizes; (void)n_in; (void)out_size;
    const float* x  = (const float*)d_in[0];
    const float* W1 = (const float*)d_in[1];
    const float* b1 = (const float*)d_in[2];
    const float* W2 = (const float*)d_in[3];
    const float* b2 = (const float*)d_in[4];
    const float* Wg = (const float*)d_in[5];
    const float* bg = (const float*)d_in[6];
    float* out = (float*)d_out;

    cvt_w1_kernel<<<(E_DIM * H_DIM * D_DIM + 255) / 256, 256>>>(W1);
    cvt_w2_kernel<<<(E_DIM * C_DIM * H_DIM + 255) / 256, 256>>>(W2);

    cudaFuncSetAttribute(moe_fused_kernel,
                         cudaFuncAttributeMaxDynamicSharedMemorySize, SMEM_TOTAL);
    moe_fused_kernel<<<B_ROWS / M_TILE, 256, SMEM_TOTAL>>>(x, b1, b2, Wg, bg, out);
}